// round 15
// baseline (speedup 1.0000x reference)
#include <cuda_runtime.h>
#include <cuda_fp16.h>
#include <cuda_bf16.h>
#include <math.h>
#include <stdint.h>

// ---------------------------------------------------------------------------
// Net_66468913873438: GCN(512->64)+ReLU -> GatedGraphConv(H=64, 2 layers)
//                     -> GCN(64->16) -> log_softmax
// N = 100000, E = 3200000.
// R15: mma_k512 double-buffered smem (1 barrier per K-chunk instead of 2).
//      R14 otherwise.
// ---------------------------------------------------------------------------

#define NMAX 100000
#define EMAX 3200000
#define CHUNK 1024

// Scratch (static device globals).
__device__ __align__(16) float   g_deg   [NMAX];
__device__ __align__(16) float   g_dinv  [NMAX];
__device__ __align__(16) float   g_hs    [NMAX * 64];
__device__ __align__(16) __half  g_hsh   [NMAX * 64];
__device__ __align__(16) __half  g_xh    [NMAX * 64];   // fp16 copy of node state
__device__ __align__(16) float   g_acc   [NMAX * 64];
__device__ __align__(16) float   g_x     [NMAX * 64];
__device__ __align__(16) float   g_hs3   [NMAX * 16];
__device__ __align__(16) __half  g_hs3h  [NMAX * 16];
__device__ __align__(16) __half  g_gi    [NMAX * 192];  // fp16 gates
__device__ __align__(16) __half  g_gh    [NMAX * 192];  // fp16 gates
__device__ __align__(16) float   g_W1T   [64 * 512];
__device__ __align__(16) float   g_Wf    [2 * 192 * 64]; // (Wg_l @ Wih^T) K-major
// CSR
__device__ __align__(16) int     g_cnt   [NMAX];
__device__ __align__(16) int     g_start [NMAX];
__device__ __align__(16) int     g_cursor[NMAX];
__device__ __align__(16) int     g_csum  [128];
__device__ __align__(16) float2  g_sw    [EMAX];

// ---------------------------------------------------------------------------
// bf16 mma.sync m16n8k16 helpers
// ---------------------------------------------------------------------------
__device__ __forceinline__ void mma16(float c[4], const uint32_t a[4],
                                      uint32_t b0, uint32_t b1) {
    asm volatile(
        "mma.sync.aligned.m16n8k16.row.col.f32.bf16.bf16.f32 "
        "{%0,%1,%2,%3}, {%4,%5,%6,%7}, {%8,%9}, {%0,%1,%2,%3};"
        : "+f"(c[0]), "+f"(c[1]), "+f"(c[2]), "+f"(c[3])
        : "r"(a[0]), "r"(a[1]), "r"(a[2]), "r"(a[3]), "r"(b0), "r"(b1));
}

struct AF { uint32_t h[4]; uint32_t l[4]; };

__device__ __forceinline__ void split2(float2 v, uint32_t& h, uint32_t& l) {
    __nv_bfloat162 hb = __floats2bfloat162_rn(v.x, v.y);
    float2 hf = __bfloat1622float2(hb);
    __nv_bfloat162 lb = __floats2bfloat162_rn(v.x - hf.x, v.y - hf.y);
    h = *(uint32_t*)&hb;
    l = *(uint32_t*)&lb;
}

__device__ __forceinline__ void load_afrag16(const float* As, int stride, int rbase,
                                             int k0, int g, int tg, AF& f) {
    const float2* p0 = (const float2*)(As + (rbase + g) * stride + k0 + 2 * tg);
    const float2* p1 = (const float2*)(As + (rbase + g + 8) * stride + k0 + 2 * tg);
    split2(p0[0], f.h[0], f.l[0]);
    split2(p1[0], f.h[1], f.l[1]);
    split2(p0[4], f.h[2], f.l[2]);
    split2(p1[4], f.h[3], f.l[3]);
}

__device__ __forceinline__ void mma_step16(const float* As, int astride, int wr,
                                           int ak0, const __nv_bfloat16* Bh,
                                           const __nv_bfloat16* Bl, int bstride,
                                           int bk0, int g, int tg, float c[2][8][4]) {
    AF fa[2];
    load_afrag16(As, astride, wr, ak0, g, tg, fa[0]);
    load_afrag16(As, astride, wr + 16, ak0, g, tg, fa[1]);
#pragma unroll
    for (int nt = 0; nt < 8; nt++) {
        int nb = (nt * 8 + g) * bstride + bk0 + 2 * tg;
        uint32_t bh0 = *(const uint32_t*)(Bh + nb);
        uint32_t bh1 = *(const uint32_t*)(Bh + nb + 8);
        uint32_t bl0 = *(const uint32_t*)(Bl + nb);
        uint32_t bl1 = *(const uint32_t*)(Bl + nb + 8);
#pragma unroll
        for (int mt = 0; mt < 2; mt++) {
            mma16(c[mt][nt], fa[mt].h, bh0, bh1);
            mma16(c[mt][nt], fa[mt].l, bh0, bh1);
            mma16(c[mt][nt], fa[mt].h, bl0, bl1);
        }
    }
}

__device__ __forceinline__ void mma_step16_m1(const float* As, int astride, int wr,
                                              int ak0, const __nv_bfloat16* Bh,
                                              const __nv_bfloat16* Bl, int bstride,
                                              int bk0, int g, int tg, float c[8][4]) {
    AF fa;
    load_afrag16(As, astride, wr, ak0, g, tg, fa);
#pragma unroll
    for (int nt = 0; nt < 8; nt++) {
        int nb = (nt * 8 + g) * bstride + bk0 + 2 * tg;
        uint32_t bh0 = *(const uint32_t*)(Bh + nb);
        uint32_t bh1 = *(const uint32_t*)(Bh + nb + 8);
        uint32_t bl0 = *(const uint32_t*)(Bl + nb);
        uint32_t bl1 = *(const uint32_t*)(Bl + nb + 8);
        mma16(c[nt], fa.h, bh0, bh1);
        mma16(c[nt], fa.l, bh0, bh1);
        mma16(c[nt], fa.h, bl0, bl1);
    }
}

__device__ __forceinline__ void store_b_split(float4 v, __nv_bfloat16* Bh,
                                              __nv_bfloat16* Bl, int off) {
    uint32_t h01, l01, h23, l23;
    split2(make_float2(v.x, v.y), h01, l01);
    split2(make_float2(v.z, v.w), h23, l23);
    *(uint2*)(Bh + off) = make_uint2(h01, h23);
    *(uint2*)(Bl + off) = make_uint2(l01, l23);
}

// ---------------------------------------------------------------------------
// Small utility kernels
// ---------------------------------------------------------------------------
__global__ void k_init(float* __restrict__ deg, int* __restrict__ cnt, int n) {
    int i = blockIdx.x * 256 + threadIdx.x;
    if (i < n) { deg[i] = 1.0f; cnt[i] = 0; }
}
__global__ void k_deg_hist(const int* __restrict__ col, const float* __restrict__ w,
                           float* __restrict__ deg, int* __restrict__ cnt, int E) {
    int e = blockIdx.x * 256 + threadIdx.x;
    if (e < E) {
        int d = col[e];
        atomicAdd(&deg[d], w[e]);
        atomicAdd(&cnt[d], 1);
    }
}
__global__ void k_dinv(const float* __restrict__ deg, float* __restrict__ dinv, int n) {
    int i = blockIdx.x * 256 + threadIdx.x;
    if (i < n) {
        float d = deg[i];
        dinv[i] = (d > 0.f) ? rsqrtf(d) : 0.f;
    }
}
__global__ void k_T512(const float* __restrict__ W, float* __restrict__ WT) {
    int idx = blockIdx.x * 256 + threadIdx.x;
    if (idx >= 512 * 64) return;
    int k = idx / 64, j = idx % 64;
    WT[j * 512 + k] = W[idx];
}
// Wf[l][j*64+k] = sum_t Wg[l][k*64+t] * Wih[j*64+t]
__global__ void k_fuseW(const float* __restrict__ Wg, const float* __restrict__ Wih,
                        float* __restrict__ Wf) {
    int idx = blockIdx.x * 256 + threadIdx.x;
    if (idx >= 2 * 192 * 64) return;
    int l = idx / (192 * 64);
    int rem = idx % (192 * 64);
    int j = rem / 64, k = rem % 64;
    const float* wg = Wg + l * 4096 + k * 64;
    const float* wi = Wih + j * 64;
    float s = 0.f;
#pragma unroll 8
    for (int t = 0; t < 64; t++) s += wg[t] * wi[t];
    Wf[idx] = s;
}

// ---------------------------------------------------------------------------
// CSR build
// ---------------------------------------------------------------------------
__global__ void k_scan_chunk(const int* __restrict__ cnt, int* __restrict__ start,
                             int* __restrict__ csum, int n) {
    __shared__ int sm[CHUNK];
    int base = blockIdx.x * CHUNK;
    int t = threadIdx.x;
    int v = (base + t < n) ? cnt[base + t] : 0;
    sm[t] = v;
    __syncthreads();
#pragma unroll
    for (int off = 1; off < CHUNK; off <<= 1) {
        int x = (t >= off) ? sm[t - off] : 0;
        __syncthreads();
        sm[t] += x;
        __syncthreads();
    }
    if (base + t < n) start[base + t] = sm[t] - v;
    if (t == CHUNK - 1) csum[blockIdx.x] = sm[t];
}
__global__ void k_scan_sums(int* __restrict__ csum, int nch) {
    __shared__ int s[128];
    int t = threadIdx.x;
    int v = (t < nch) ? csum[t] : 0;
    s[t] = v;
    __syncthreads();
#pragma unroll
    for (int off = 1; off < 128; off <<= 1) {
        int x = (t >= off) ? s[t - off] : 0;
        __syncthreads();
        s[t] += x;
        __syncthreads();
    }
    if (t < nch) csum[t] = s[t] - v;
}
__global__ void k_scan_add(int* __restrict__ start, int* __restrict__ cursor,
                           const int* __restrict__ csum, int n) {
    int i = blockIdx.x * 256 + threadIdx.x;
    if (i < n) {
        int s = start[i] + csum[i >> 10];
        start[i] = s;
        cursor[i] = s;
    }
}
__global__ void k_reorder(const int* __restrict__ row, const int* __restrict__ col,
                          const float* __restrict__ w, int* __restrict__ cursor,
                          float2* __restrict__ sw, int E) {
    int e = blockIdx.x * 256 + threadIdx.x;
    if (e >= E) return;
    int d = col[e];
    int pos = atomicAdd(&cursor[d], 1);
    sw[pos] = make_float2(__int_as_float(row[e]), w[e]);
}

// ---------------------------------------------------------------------------
// bf16x3 GEMM, K=512, BM=128, warp-tile 16x64, double-buffered smem
// (1 barrier per K-chunk). hs = rsqrt(deg)*(x@W1T^T); fp32 + fp16 out.
// ---------------------------------------------------------------------------
#define K512_BUF (128 * 36 * 4 + 2 * 64 * 40 * 2)   // 28672 B per buffer
#define K512_SMEM (2 * K512_BUF)

__global__ __launch_bounds__(256) void mma_k512(
    const float4* __restrict__ A4, const float4* __restrict__ B4,
    float* __restrict__ out, __half* __restrict__ outh,
    const float* __restrict__ deg, int M)
{
    extern __shared__ char smc[];

    int tid = threadIdx.x, wid = tid >> 5, lane = tid & 31;
    int g = lane >> 2, tg = lane & 3;
    int blk = blockIdx.x;
    int wr = wid * 16;

    float c[8][4];
#pragma unroll
    for (int nt = 0; nt < 8; nt++)
#pragma unroll
        for (int i = 0; i < 4; i++) c[nt][i] = 0.f;

    // per-thread load indices
    const int rA = tid >> 3, qA = tid & 7;        // A: 4 rows/thread via it*32
    float4 va[4], vb[2];

    // prefetch + store chunk 0 into buf 0
#pragma unroll
    for (int it = 0; it < 4; it++) {
        int r = it * 32 + rA;
        int gm = blk * 128 + r;
        va[it] = (gm < M) ? A4[(size_t)gm * 128 + qA]
                          : make_float4(0.f, 0.f, 0.f, 0.f);
    }
#pragma unroll
    for (int it = 0; it < 2; it++) {
        int r = it * 32 + rA;
        vb[it] = B4[(size_t)r * 128 + qA];
    }
    {
        float* As0 = (float*)smc;
        __nv_bfloat16* Bh0 = (__nv_bfloat16*)(smc + 128 * 36 * 4);
        __nv_bfloat16* Bl0 = Bh0 + 64 * 40;
#pragma unroll
        for (int it = 0; it < 4; it++)
            *(float4*)(As0 + (it * 32 + rA) * 36 + qA * 4) = va[it];
#pragma unroll
        for (int it = 0; it < 2; it++)
            store_b_split(vb[it], Bh0, Bl0, (it * 32 + rA) * 40 + qA * 4);
    }
    __syncthreads();

    for (int kc = 0; kc < 16; kc++) {
        char* cur = smc + (kc & 1) * K512_BUF;
        char* nxt = smc + ((kc + 1) & 1) * K512_BUF;
        float* As = (float*)cur;
        __nv_bfloat16* Bh = (__nv_bfloat16*)(cur + 128 * 36 * 4);
        __nv_bfloat16* Bl = Bh + 64 * 40;

        if (kc < 15) {   // global prefetch of next chunk (overlaps mma)
#pragma unroll
            for (int it = 0; it < 4; it++) {
                int r = it * 32 + rA;
                int gm = blk * 128 + r;
                va[it] = (gm < M) ? A4[(size_t)gm * 128 + (kc + 1) * 8 + qA]
                                  : make_float4(0.f, 0.f, 0.f, 0.f);
            }
#pragma unroll
            for (int it = 0; it < 2; it++) {
                int r = it * 32 + rA;
                vb[it] = B4[(size_t)r * 128 + (kc + 1) * 8 + qA];
            }
        }

#pragma unroll
        for (int s = 0; s < 2; s++)
            mma_step16_m1(As, 36, wr, s * 16, Bh, Bl, 40, s * 16, g, tg, c);

        if (kc < 15) {   // store next chunk into the other buffer
            float* AsN = (float*)nxt;
            __nv_bfloat16* BhN = (__nv_bfloat16*)(nxt + 128 * 36 * 4);
            __nv_bfloat16* BlN = BhN + 64 * 40;
#pragma unroll
            for (int it = 0; it < 4; it++)
                *(float4*)(AsN + (it * 32 + rA) * 36 + qA * 4) = va[it];
#pragma unroll
            for (int it = 0; it < 2; it++)
                store_b_split(vb[it], BhN, BlN, (it * 32 + rA) * 40 + qA * 4);
        }
        __syncthreads();
    }

    int r0 = blk * 128 + wr + g;
    int r1 = r0 + 8;
    float d0 = (r0 < M) ? deg[r0] : 1.f;
    float d1 = (r1 < M) ? deg[r1] : 1.f;
    float dv0 = (d0 > 0.f) ? rsqrtf(d0) : 0.f;
    float dv1 = (d1 > 0.f) ? rsqrtf(d1) : 0.f;
#pragma unroll
    for (int nt = 0; nt < 8; nt++) {
        int cb = nt * 8 + 2 * tg;
        if (r0 < M) {
            float v0 = dv0 * c[nt][0], v1 = dv0 * c[nt][1];
            *(float2*)(out + (size_t)r0 * 64 + cb) = make_float2(v0, v1);
            *(__half2*)(outh + (size_t)r0 * 64 + cb) = __floats2half2_rn(v0, v1);
        }
        if (r1 < M) {
            float v2 = dv1 * c[nt][2], v3 = dv1 * c[nt][3];
            *(float2*)(out + (size_t)r1 * 64 + cb) = make_float2(v2, v3);
            *(__half2*)(outh + (size_t)r1 * 64 + cb) = __floats2half2_rn(v2, v3);
        }
    }
}

// ---------------------------------------------------------------------------
// bf16x3 GEMM, K=64, fp16 output (stride ncols). A resident in smem.
// ---------------------------------------------------------------------------
#define K64_SMEM (256 * 68 * 4 + 2 * 64 * 72 * 2)

__global__ __launch_bounds__(256) void mma_k64h(
    const float4* __restrict__ A4, const float4* __restrict__ B4,
    __half* __restrict__ outH, int M, int ncols)
{
    extern __shared__ float smf[];
    float* As = smf;
    __nv_bfloat16* Bh = (__nv_bfloat16*)(smf + 256 * 68);
    __nv_bfloat16* Bl = Bh + 64 * 72;

    int tid = threadIdx.x, wid = tid >> 5, lane = tid & 31;
    int g = lane >> 2, tg = lane & 3;
    int blk = blockIdx.x;
    int wr = wid * 32;

#pragma unroll
    for (int it = 0; it < 16; it++) {
        int idx = it * 256 + tid;
        int r = idx >> 4, q = idx & 15;
        int gm = blk * 256 + r;
        float4 v = (gm < M) ? A4[(size_t)gm * 16 + q]
                            : make_float4(0.f, 0.f, 0.f, 0.f);
        *(float4*)(As + r * 68 + q * 4) = v;
    }
    __syncthreads();

    int ntilesc = ncols >> 6;
    for (int ct = 0; ct < ntilesc; ct++) {
#pragma unroll
        for (int it = 0; it < 4; it++) {
            int idx = it * 256 + tid;
            int r = idx >> 4, q = idx & 15;
            float4 v = B4[(size_t)(ct * 64 + r) * 16 + q];
            store_b_split(v, Bh, Bl, r * 72 + q * 4);
        }
        __syncthreads();

        float c[2][8][4];
#pragma unroll
        for (int mt = 0; mt < 2; mt++)
#pragma unroll
            for (int nt = 0; nt < 8; nt++)
#pragma unroll
                for (int i = 0; i < 4; i++) c[mt][nt][i] = 0.f;

#pragma unroll
        for (int s = 0; s < 4; s++)
            mma_step16(As, 68, wr, s * 16, Bh, Bl, 72, s * 16, g, tg, c);

#pragma unroll
        for (int mt = 0; mt < 2; mt++) {
            int r0 = blk * 256 + wr + mt * 16 + g;
            int r1 = r0 + 8;
#pragma unroll
            for (int nt = 0; nt < 8; nt++) {
                int cb = ct * 64 + nt * 8 + 2 * tg;
                if (r0 < M)
                    *(__half2*)(outH + (size_t)r0 * ncols + cb) =
                        __floats2half2_rn(c[mt][nt][0], c[mt][nt][1]);
                if (r1 < M)
                    *(__half2*)(outH + (size_t)r1 * ncols + cb) =
                        __floats2half2_rn(c[mt][nt][2], c[mt][nt][3]);
            }
        }
        __syncthreads();
    }
}

// ---------------------------------------------------------------------------
// CSR gather, fp16 features, 64-wide. 8 lanes/dest, uint4 (16B) loads.
// ---------------------------------------------------------------------------
__device__ __forceinline__ void h8_acc(uint4 u, float w, float* a) {
    float2 p0 = __half22float2(*(__half2*)&u.x);
    float2 p1 = __half22float2(*(__half2*)&u.y);
    float2 p2 = __half22float2(*(__half2*)&u.z);
    float2 p3 = __half22float2(*(__half2*)&u.w);
    a[0] += w * p0.x; a[1] += w * p0.y;
    a[2] += w * p1.x; a[3] += w * p1.y;
    a[4] += w * p2.x; a[5] += w * p2.y;
    a[6] += w * p3.x; a[7] += w * p3.y;
}

__global__ void gather64h(const int* __restrict__ start, const int* __restrict__ cnt,
                          const float2* __restrict__ sw, const __half* __restrict__ feat,
                          const float4* __restrict__ hs4, const float* __restrict__ dinv,
                          const float* __restrict__ b1, float4* __restrict__ out4,
                          __half* __restrict__ outh, int N, int mode) {
    int gid = blockIdx.x * 256 + threadIdx.x;
    int d = gid >> 3;
    int q = gid & 7;
    if (d >= N) return;

    int j = start[d];
    int end = j + cnt[d];
    float a[8] = {0.f, 0.f, 0.f, 0.f, 0.f, 0.f, 0.f, 0.f};

#pragma unroll 1
    for (; j + 3 < end; j += 4) {
        float2 p0 = __ldg(&sw[j]);
        float2 p1 = __ldg(&sw[j + 1]);
        float2 p2 = __ldg(&sw[j + 2]);
        float2 p3 = __ldg(&sw[j + 3]);
        uint4 u0 = *(const uint4*)(feat + (size_t)__float_as_int(p0.x) * 64 + q * 8);
        uint4 u1 = *(const uint4*)(feat + (size_t)__float_as_int(p1.x) * 64 + q * 8);
        uint4 u2 = *(const uint4*)(feat + (size_t)__float_as_int(p2.x) * 64 + q * 8);
        uint4 u3 = *(const uint4*)(feat + (size_t)__float_as_int(p3.x) * 64 + q * 8);
        h8_acc(u0, p0.y, a);
        h8_acc(u1, p1.y, a);
        h8_acc(u2, p2.y, a);
        h8_acc(u3, p3.y, a);
    }
    for (; j < end; j++) {
        float2 p = __ldg(&sw[j]);
        uint4 u = *(const uint4*)(feat + (size_t)__float_as_int(p.x) * 64 + q * 8);
        h8_acc(u, p.y, a);
    }

    int o = d * 16 + q * 2;
    if (mode == 1) {
        float di = dinv[d];
        float4 h0 = hs4[o];
        float4 h1 = hs4[o + 1];
        float4 bb0 = ((const float4*)b1)[q * 2];
        float4 bb1 = ((const float4*)b1)[q * 2 + 1];
        a[0] = fmaxf(di * (a[0] + h0.x) + bb0.x, 0.f);
        a[1] = fmaxf(di * (a[1] + h0.y) + bb0.y, 0.f);
        a[2] = fmaxf(di * (a[2] + h0.z) + bb0.z, 0.f);
        a[3] = fmaxf(di * (a[3] + h0.w) + bb0.w, 0.f);
        a[4] = fmaxf(di * (a[4] + h1.x) + bb1.x, 0.f);
        a[5] = fmaxf(di * (a[5] + h1.y) + bb1.y, 0.f);
        a[6] = fmaxf(di * (a[6] + h1.z) + bb1.z, 0.f);
        a[7] = fmaxf(di * (a[7] + h1.w) + bb1.w, 0.f);
        __half2 c0 = __floats2half2_rn(a[0], a[1]);
        __half2 c1 = __floats2half2_rn(a[2], a[3]);
        __half2 c2 = __floats2half2_rn(a[4], a[5]);
        __half2 c3 = __floats2half2_rn(a[6], a[7]);
        uint4 uo;
        uo.x = *(uint32_t*)&c0; uo.y = *(uint32_t*)&c1;
        uo.z = *(uint32_t*)&c2; uo.w = *(uint32_t*)&c3;
        *(uint4*)(outh + (size_t)d * 64 + q * 8) = uo;
    }
    out4[o]     = make_float4(a[0], a[1], a[2], a[3]);
    out4[o + 1] = make_float4(a[4], a[5], a[6], a[7]);
}

// ---------------------------------------------------------------------------
// GRU elementwise combine (fp16 gates, 2 features/thread)
// ---------------------------------------------------------------------------
__global__ void gru_combine(const __half* __restrict__ gi, const __half* __restrict__ gh,
                            const float* __restrict__ bih, const float* __restrict__ bhh,
                            float* __restrict__ x, __half* __restrict__ xh, int n) {
    int i = blockIdx.x * 256 + threadIdx.x;
    if (i >= n * 32) return;
    int nd = i >> 5, f = (i & 31) * 2;
    size_t b = (size_t)nd * 192;

    float2 gir = __half22float2(*(const __half2*)(gi + b + f));
    float2 giz = __half22float2(*(const __half2*)(gi + b + 64 + f));
    float2 gin = __half22float2(*(const __half2*)(gi + b + 128 + f));
    float2 ghr = __half22float2(*(const __half2*)(gh + b + f));
    float2 ghz = __half22float2(*(const __half2*)(gh + b + 64 + f));
    float2 ghn = __half22float2(*(const __half2*)(gh + b + 128 + f));
    float2 bir = *(const float2*)(bih + f);
    float2 biz = *(const float2*)(bih + 64 + f);
    float2 bin = *(const float2*)(bih + 128 + f);
    float2 bhr = *(const float2*)(bhh + f);
    float2 bhz = *(const float2*)(bhh + 64 + f);
    float2 bhn = *(const float2*)(bhh + 128 + f);

    float r0 = 1.f / (1.f + expf(-(gir.x + bir.x + ghr.x + bhr.x)));
    float r1 = 1.f / (1.f + expf(-(gir.y + bir.y + ghr.y + bhr.y)));
    float z0 = 1.f / (1.f + expf(-(giz.x + biz.x + ghz.x + bhz.x)));
    float z1 = 1.f / (1.f + expf(-(giz.y + biz.y + ghz.y + bhz.y)));
    float n0 = tanhf(gin.x + bin.x + r0 * (ghn.x + bhn.x));
    float n1 = tanhf(gin.y + bin.y + r1 * (ghn.y + bhn.y));

    size_t xi = (size_t)nd * 64 + f;
    float2 xv = *(float2*)(x + xi);
    xv.x = (1.f - z0) * n0 + z0 * xv.x;
    xv.y = (1.f - z1) * n1 + z1 * xv.y;
    *(float2*)(x + xi) = xv;
    *(__half2*)(xh + xi) = __floats2half2_rn(xv.x, xv.y);
}

// ---------------------------------------------------------------------------
// GCN2 linear (writes fp32 + fp16)
// ---------------------------------------------------------------------------
__global__ void gemm_out16(const float* __restrict__ x, const float* __restrict__ W2,
                           const float* __restrict__ dinv, float* __restrict__ hs3,
                           __half* __restrict__ hs3h, int nrows) {
    __shared__ float w2s[64 * 16];
    int tid = threadIdx.x;
    for (int i = tid; i < 64 * 16; i += 256) w2s[i] = W2[i];
    __syncthreads();

    int node = blockIdx.x * 16 + (tid >> 4);
    int c = tid & 15;
    if (node >= nrows) return;
    const float* xr = x + (size_t)node * 64;
    float s = 0.f;
#pragma unroll
    for (int k = 0; k < 64; k++) s += xr[k] * w2s[k * 16 + c];
    float v = dinv[node] * s;
    hs3[(size_t)node * 16 + c] = v;
    hs3h[(size_t)node * 16 + c] = __float2half_rn(v);
}

// ---------------------------------------------------------------------------
// Fused GCN2 gather + log_softmax finalize. 4 lanes/dest; shfl reduction.
// ---------------------------------------------------------------------------
__global__ void k_final_gather(const int* __restrict__ start, const int* __restrict__ cnt,
                               const float2* __restrict__ sw,
                               const __half* __restrict__ feat,
                               const float* __restrict__ hs3,
                               const float* __restrict__ dinv,
                               const float* __restrict__ b2,
                               float* __restrict__ out, int N) {
    int gid = blockIdx.x * 256 + threadIdx.x;
    int d = gid >> 2;
    int q = gid & 3;
    if (d >= N) return;

    int j = start[d];
    int end = j + cnt[d];
    float4 acc = make_float4(0.f, 0.f, 0.f, 0.f);

    for (; j + 1 < end; j += 2) {
        float2 p0 = __ldg(&sw[j]);
        float2 p1 = __ldg(&sw[j + 1]);
        uint2 u0 = *(const uint2*)(feat + (size_t)__float_as_int(p0.x) * 16 + q * 4);
        uint2 u1 = *(const uint2*)(feat + (size_t)__float_as_int(p1.x) * 16 + q * 4);
        float2 a0 = __half22float2(*(__half2*)&u0.x), b0 = __half22float2(*(__half2*)&u0.y);
        float2 a1 = __half22float2(*(__half2*)&u1.x), b1v = __half22float2(*(__half2*)&u1.y);
        acc.x += p0.y * a0.x; acc.y += p0.y * a0.y; acc.z += p0.y * b0.x; acc.w += p0.y * b0.y;
        acc.x += p1.y * a1.x; acc.y += p1.y * a1.y; acc.z += p1.y * b1v.x; acc.w += p1.y * b1v.y;
    }
    if (j < end) {
        float2 p = __ldg(&sw[j]);
        uint2 u = *(const uint2*)(feat + (size_t)__float_as_int(p.x) * 16 + q * 4);
        float2 a = __half22float2(*(__half2*)&u.x), b = __half22float2(*(__half2*)&u.y);
        acc.x += p.y * a.x; acc.y += p.y * a.y;
        acc.z += p.y * b.x; acc.w += p.y * b.y;
    }

    float di = dinv[d];
    float4 h = *(const float4*)(hs3 + (size_t)d * 16 + q * 4);
    float4 bb = ((const float4*)b2)[q];
    float v0 = di * (acc.x + h.x) + bb.x;
    float v1 = di * (acc.y + h.y) + bb.y;
    float v2 = di * (acc.z + h.z) + bb.z;
    float v3 = di * (acc.w + h.w) + bb.w;

    float mx = fmaxf(fmaxf(v0, v1), fmaxf(v2, v3));
    mx = fmaxf(mx, __shfl_xor_sync(0xFFFFFFFFu, mx, 1));
    mx = fmaxf(mx, __shfl_xor_sync(0xFFFFFFFFu, mx, 2));
    float sum = expf(v0 - mx) + expf(v1 - mx) + expf(v2 - mx) + expf(v3 - mx);
    sum += __shfl_xor_sync(0xFFFFFFFFu, sum, 1);
    sum += __shfl_xor_sync(0xFFFFFFFFu, sum, 2);
    float l = mx + logf(sum);

    *(float4*)(out + (size_t)d * 16 + q * 4) =
        make_float4(v0 - l, v1 - l, v2 - l, v3 - l);
}

// ---------------------------------------------------------------------------
// Launch sequence with dual-stream overlap (capture-safe fork/join).
// ---------------------------------------------------------------------------
extern "C" void kernel_launch(void* const* d_in, const int* in_sizes, int n_in,
                              void* d_out, int out_size) {
    const float* x   = (const float*)d_in[0];
    const int*   ei  = (const int*)d_in[1];
    const float* ew  = (const float*)d_in[2];
    const float* W1  = (const float*)d_in[3];
    const float* b1  = (const float*)d_in[4];
    const float* Wg  = (const float*)d_in[5];
    const float* Wih = (const float*)d_in[6];
    const float* Whh = (const float*)d_in[7];
    const float* bih = (const float*)d_in[8];
    const float* bhh = (const float*)d_in[9];
    const float* W2  = (const float*)d_in[10];
    const float* b2  = (const float*)d_in[11];
    float* out = (float*)d_out;

    const int N = in_sizes[0] / 512;
    const int E = in_sizes[2];
    const int* row = ei;
    const int* col = ei + E;

    float *p_deg, *p_dinv, *p_hs, *p_acc, *p_x, *p_hs3, *p_W1T, *p_Wf;
    __half *p_hsh, *p_xh, *p_hs3h, *p_gi, *p_gh;
    int *p_cnt, *p_start, *p_cursor, *p_csum;
    float2* p_sw;
    cudaGetSymbolAddress((void**)&p_deg,    g_deg);
    cudaGetSymbolAddress((void**)&p_dinv,   g_dinv);
    cudaGetSymbolAddress((void**)&p_hs,     g_hs);
    cudaGetSymbolAddress((void**)&p_hsh,    g_hsh);
    cudaGetSymbolAddress((void**)&p_xh,     g_xh);
    cudaGetSymbolAddress((void**)&p_acc,    g_acc);
    cudaGetSymbolAddress((void**)&p_x,      g_x);
    cudaGetSymbolAddress((void**)&p_hs3,    g_hs3);
    cudaGetSymbolAddress((void**)&p_hs3h,   g_hs3h);
    cudaGetSymbolAddress((void**)&p_gi,     g_gi);
    cudaGetSymbolAddress((void**)&p_gh,     g_gh);
    cudaGetSymbolAddress((void**)&p_W1T,    g_W1T);
    cudaGetSymbolAddress((void**)&p_Wf,     g_Wf);
    cudaGetSymbolAddress((void**)&p_cnt,    g_cnt);
    cudaGetSymbolAddress((void**)&p_start,  g_start);
    cudaGetSymbolAddress((void**)&p_cursor, g_cursor);
    cudaGetSymbolAddress((void**)&p_csum,   g_csum);
    cudaGetSymbolAddress((void**)&p_sw,     g_sw);

    cudaFuncSetAttribute(mma_k512, cudaFuncAttributeMaxDynamicSharedMemorySize, K512_SMEM);
    cudaFuncSetAttribute(mma_k64h, cudaFuncAttributeMaxDynamicSharedMemorySize, K64_SMEM);

    static cudaStream_t s2 = 0;
    static cudaEvent_t evf[3], evj[3];
    if (s2 == 0) {
        cudaStreamCreateWithFlags(&s2, cudaStreamNonBlocking);
        for (int i = 0; i < 3; i++) {
            cudaEventCreateWithFlags(&evf[i], cudaEventDisableTiming);
            cudaEventCreateWithFlags(&evj[i], cudaEventDisableTiming);
        }
    }

    const int nblkN    = (N + 255) / 256;
    const int nblkE    = (E + 255) / 256;
    const int nblkM128 = (N + 127) / 128;
    const int nblkM256 = (N + 255) / 256;
    const int nblk16   = (N + 15) / 16;
    const int nchunks  = (N + CHUNK - 1) / CHUNK;
    const int nblkG64  = (N * 8 + 255) / 256;
    const int nblkG4   = (N * 4 + 255) / 256;
    const int nblkC    = (N * 32 + 255) / 256;

    // --- main stream: prerequisites for the big GEMM ---
    k_T512<<<(512 * 64 + 255) / 256, 256>>>(W1, p_W1T);
    k_init<<<nblkN, 256>>>(p_deg, p_cnt, N);
    k_deg_hist<<<nblkE, 256>>>(col, ew, p_deg, p_cnt, E);

    // fork: CSR build + weight prep on s2, concurrent with mma_k512
    cudaEventRecord(evf[0], 0);
    cudaStreamWaitEvent(s2, evf[0], 0);

    mma_k512<<<nblkM128, 256, K512_SMEM>>>((const float4*)x, (const float4*)p_W1T,
                                           p_hs, p_hsh, p_deg, N);

    k_dinv<<<nblkN, 256, 0, s2>>>(p_deg, p_dinv, N);
    k_fuseW<<<(2 * 192 * 64 + 255) / 256, 256, 0, s2>>>(Wg, Wih, p_Wf);
    k_scan_chunk<<<nchunks, CHUNK, 0, s2>>>(p_cnt, p_start, p_csum, N);
    k_scan_sums<<<1, 128, 0, s2>>>(p_csum, nchunks);
    k_scan_add<<<nblkN, 256, 0, s2>>>(p_start, p_cursor, p_csum, N);
    k_reorder<<<nblkE, 256, 0, s2>>>(row, col, ew, p_cursor, p_sw, E);
    cudaEventRecord(evj[0], s2);
    cudaStreamWaitEvent(0, evj[0], 0);

    // GCN1 gather: x = relu(...), also writes xh fp16
    gather64h<<<nblkG64, 256>>>(p_start, p_cnt, p_sw, p_hsh,
                                (const float4*)p_hs, p_dinv, b1,
                                (float4*)p_x, p_xh, N, 1);

    // GatedGraphConv: 2 layers; gh-GEMM overlapped on s2
    for (int l = 0; l < 2; l++) {
        cudaEventRecord(evf[1 + l], 0);
        cudaStreamWaitEvent(s2, evf[1 + l], 0);
        // s2: gh = x @ Whh^T (fp16, 192 cols)
        mma_k64h<<<nblkM256, 256, K64_SMEM, s2>>>((const float4*)p_x,
                                                  (const float4*)Whh, p_gh, N, 192);
        // main: xagg = gather(xh); gi = xagg @ Wf_l (fp16, 192 cols)
        gather64h<<<nblkG64, 256>>>(p_start, p_cnt, p_sw, p_xh,
                                    (const float4*)0, (const float*)0, (const float*)0,
                                    (float4*)p_acc, (__half*)0, N, 0);
        mma_k64h<<<nblkM256, 256, K64_SMEM>>>((const float4*)p_acc,
                                              (const float4*)(p_Wf + (size_t)l * 192 * 64),
                                              p_gi, N, 192);
        cudaEventRecord(evj[1 + l], s2);
        cudaStreamWaitEvent(0, evj[1 + l], 0);
        gru_combine<<<nblkC, 256>>>(p_gi, p_gh, bih, bhh, p_x, p_xh, N);
    }

    // GCN layer 2 + fused gather/log_softmax
    gemm_out16<<<nblk16, 256>>>(p_x, W2, p_dinv, p_hs3, p_hs3h, N);
    k_final_gather<<<nblkG4, 256>>>(p_start, p_cnt, p_sw, p_hs3h, p_hs3,
                                    p_dinv, b2, out, N);
}

// round 16
// speedup vs baseline: 1.0455x; 1.0455x over previous
#include <cuda_runtime.h>
#include <cuda_fp16.h>
#include <cuda_bf16.h>
#include <math.h>
#include <stdint.h>

// ---------------------------------------------------------------------------
// Net_66468913873438: GCN(512->64)+ReLU -> GatedGraphConv(H=64, 2 layers)
//                     -> GCN(64->16) -> log_softmax
// N = 100000, E = 3200000.
// R16: revert k512 to R14 single-buffer (R15 double-buffer regressed);
//      node state kept fp16-only (xh) — fp32 x stream eliminated.
// ---------------------------------------------------------------------------

#define NMAX 100000
#define EMAX 3200000
#define CHUNK 1024

// Scratch (static device globals).
__device__ __align__(16) float   g_deg   [NMAX];
__device__ __align__(16) float   g_dinv  [NMAX];
__device__ __align__(16) float   g_hs    [NMAX * 64];   // gemm1 fp32 self term
__device__ __align__(16) __half  g_hsh   [NMAX * 64];   // fp16 copy for gather
__device__ __align__(16) __half  g_xh    [NMAX * 64];   // node state (fp16 only)
__device__ __align__(16) float   g_acc   [NMAX * 64];
__device__ __align__(16) float   g_hs3   [NMAX * 16];
__device__ __align__(16) __half  g_hs3h  [NMAX * 16];
__device__ __align__(16) __half  g_gi    [NMAX * 192];  // fp16 gates
__device__ __align__(16) __half  g_gh    [NMAX * 192];  // fp16 gates
__device__ __align__(16) float   g_W1T   [64 * 512];
__device__ __align__(16) float   g_Wf    [2 * 192 * 64]; // (Wg_l @ Wih^T) K-major
// CSR
__device__ __align__(16) int     g_cnt   [NMAX];
__device__ __align__(16) int     g_start [NMAX];
__device__ __align__(16) int     g_cursor[NMAX];
__device__ __align__(16) int     g_csum  [128];
__device__ __align__(16) float2  g_sw    [EMAX];

// ---------------------------------------------------------------------------
// bf16 mma.sync m16n8k16 helpers
// ---------------------------------------------------------------------------
__device__ __forceinline__ void mma16(float c[4], const uint32_t a[4],
                                      uint32_t b0, uint32_t b1) {
    asm volatile(
        "mma.sync.aligned.m16n8k16.row.col.f32.bf16.bf16.f32 "
        "{%0,%1,%2,%3}, {%4,%5,%6,%7}, {%8,%9}, {%0,%1,%2,%3};"
        : "+f"(c[0]), "+f"(c[1]), "+f"(c[2]), "+f"(c[3])
        : "r"(a[0]), "r"(a[1]), "r"(a[2]), "r"(a[3]), "r"(b0), "r"(b1));
}

struct AF { uint32_t h[4]; uint32_t l[4]; };

__device__ __forceinline__ void split2(float2 v, uint32_t& h, uint32_t& l) {
    __nv_bfloat162 hb = __floats2bfloat162_rn(v.x, v.y);
    float2 hf = __bfloat1622float2(hb);
    __nv_bfloat162 lb = __floats2bfloat162_rn(v.x - hf.x, v.y - hf.y);
    h = *(uint32_t*)&hb;
    l = *(uint32_t*)&lb;
}

__device__ __forceinline__ void load_afrag16(const float* As, int stride, int rbase,
                                             int k0, int g, int tg, AF& f) {
    const float2* p0 = (const float2*)(As + (rbase + g) * stride + k0 + 2 * tg);
    const float2* p1 = (const float2*)(As + (rbase + g + 8) * stride + k0 + 2 * tg);
    split2(p0[0], f.h[0], f.l[0]);
    split2(p1[0], f.h[1], f.l[1]);
    split2(p0[4], f.h[2], f.l[2]);
    split2(p1[4], f.h[3], f.l[3]);
}

__device__ __forceinline__ void mma_step16(const float* As, int astride, int wr,
                                           int ak0, const __nv_bfloat16* Bh,
                                           const __nv_bfloat16* Bl, int bstride,
                                           int bk0, int g, int tg, float c[2][8][4]) {
    AF fa[2];
    load_afrag16(As, astride, wr, ak0, g, tg, fa[0]);
    load_afrag16(As, astride, wr + 16, ak0, g, tg, fa[1]);
#pragma unroll
    for (int nt = 0; nt < 8; nt++) {
        int nb = (nt * 8 + g) * bstride + bk0 + 2 * tg;
        uint32_t bh0 = *(const uint32_t*)(Bh + nb);
        uint32_t bh1 = *(const uint32_t*)(Bh + nb + 8);
        uint32_t bl0 = *(const uint32_t*)(Bl + nb);
        uint32_t bl1 = *(const uint32_t*)(Bl + nb + 8);
#pragma unroll
        for (int mt = 0; mt < 2; mt++) {
            mma16(c[mt][nt], fa[mt].h, bh0, bh1);
            mma16(c[mt][nt], fa[mt].l, bh0, bh1);
            mma16(c[mt][nt], fa[mt].h, bl0, bl1);
        }
    }
}

__device__ __forceinline__ void mma_step16_m1(const float* As, int astride, int wr,
                                              int ak0, const __nv_bfloat16* Bh,
                                              const __nv_bfloat16* Bl, int bstride,
                                              int bk0, int g, int tg, float c[8][4]) {
    AF fa;
    load_afrag16(As, astride, wr, ak0, g, tg, fa);
#pragma unroll
    for (int nt = 0; nt < 8; nt++) {
        int nb = (nt * 8 + g) * bstride + bk0 + 2 * tg;
        uint32_t bh0 = *(const uint32_t*)(Bh + nb);
        uint32_t bh1 = *(const uint32_t*)(Bh + nb + 8);
        uint32_t bl0 = *(const uint32_t*)(Bl + nb);
        uint32_t bl1 = *(const uint32_t*)(Bl + nb + 8);
        mma16(c[nt], fa.h, bh0, bh1);
        mma16(c[nt], fa.l, bh0, bh1);
        mma16(c[nt], fa.h, bl0, bl1);
    }
}

__device__ __forceinline__ void store_b_split(float4 v, __nv_bfloat16* Bh,
                                              __nv_bfloat16* Bl, int off) {
    uint32_t h01, l01, h23, l23;
    split2(make_float2(v.x, v.y), h01, l01);
    split2(make_float2(v.z, v.w), h23, l23);
    *(uint2*)(Bh + off) = make_uint2(h01, h23);
    *(uint2*)(Bl + off) = make_uint2(l01, l23);
}

// ---------------------------------------------------------------------------
// Small utility kernels
// ---------------------------------------------------------------------------
__global__ void k_init(float* __restrict__ deg, int* __restrict__ cnt, int n) {
    int i = blockIdx.x * 256 + threadIdx.x;
    if (i < n) { deg[i] = 1.0f; cnt[i] = 0; }
}
__global__ void k_deg_hist(const int* __restrict__ col, const float* __restrict__ w,
                           float* __restrict__ deg, int* __restrict__ cnt, int E) {
    int e = blockIdx.x * 256 + threadIdx.x;
    if (e < E) {
        int d = col[e];
        atomicAdd(&deg[d], w[e]);
        atomicAdd(&cnt[d], 1);
    }
}
__global__ void k_dinv(const float* __restrict__ deg, float* __restrict__ dinv, int n) {
    int i = blockIdx.x * 256 + threadIdx.x;
    if (i < n) {
        float d = deg[i];
        dinv[i] = (d > 0.f) ? rsqrtf(d) : 0.f;
    }
}
__global__ void k_T512(const float* __restrict__ W, float* __restrict__ WT) {
    int idx = blockIdx.x * 256 + threadIdx.x;
    if (idx >= 512 * 64) return;
    int k = idx / 64, j = idx % 64;
    WT[j * 512 + k] = W[idx];
}
// Wf[l][j*64+k] = sum_t Wg[l][k*64+t] * Wih[j*64+t]
__global__ void k_fuseW(const float* __restrict__ Wg, const float* __restrict__ Wih,
                        float* __restrict__ Wf) {
    int idx = blockIdx.x * 256 + threadIdx.x;
    if (idx >= 2 * 192 * 64) return;
    int l = idx / (192 * 64);
    int rem = idx % (192 * 64);
    int j = rem / 64, k = rem % 64;
    const float* wg = Wg + l * 4096 + k * 64;
    const float* wi = Wih + j * 64;
    float s = 0.f;
#pragma unroll 8
    for (int t = 0; t < 64; t++) s += wg[t] * wi[t];
    Wf[idx] = s;
}

// ---------------------------------------------------------------------------
// CSR build
// ---------------------------------------------------------------------------
__global__ void k_scan_chunk(const int* __restrict__ cnt, int* __restrict__ start,
                             int* __restrict__ csum, int n) {
    __shared__ int sm[CHUNK];
    int base = blockIdx.x * CHUNK;
    int t = threadIdx.x;
    int v = (base + t < n) ? cnt[base + t] : 0;
    sm[t] = v;
    __syncthreads();
#pragma unroll
    for (int off = 1; off < CHUNK; off <<= 1) {
        int x = (t >= off) ? sm[t - off] : 0;
        __syncthreads();
        sm[t] += x;
        __syncthreads();
    }
    if (base + t < n) start[base + t] = sm[t] - v;
    if (t == CHUNK - 1) csum[blockIdx.x] = sm[t];
}
__global__ void k_scan_sums(int* __restrict__ csum, int nch) {
    __shared__ int s[128];
    int t = threadIdx.x;
    int v = (t < nch) ? csum[t] : 0;
    s[t] = v;
    __syncthreads();
#pragma unroll
    for (int off = 1; off < 128; off <<= 1) {
        int x = (t >= off) ? s[t - off] : 0;
        __syncthreads();
        s[t] += x;
        __syncthreads();
    }
    if (t < nch) csum[t] = s[t] - v;
}
__global__ void k_scan_add(int* __restrict__ start, int* __restrict__ cursor,
                           const int* __restrict__ csum, int n) {
    int i = blockIdx.x * 256 + threadIdx.x;
    if (i < n) {
        int s = start[i] + csum[i >> 10];
        start[i] = s;
        cursor[i] = s;
    }
}
__global__ void k_reorder(const int* __restrict__ row, const int* __restrict__ col,
                          const float* __restrict__ w, int* __restrict__ cursor,
                          float2* __restrict__ sw, int E) {
    int e = blockIdx.x * 256 + threadIdx.x;
    if (e >= E) return;
    int d = col[e];
    int pos = atomicAdd(&cursor[d], 1);
    sw[pos] = make_float2(__int_as_float(row[e]), w[e]);
}

// ---------------------------------------------------------------------------
// bf16x3 GEMM, K=512, BM=128, warp-tile 16x64, prefetch-pipelined
// (R14 single-buffer version — verified fastest).
// ---------------------------------------------------------------------------
#define K512_SMEM (128 * 36 * 4 + 2 * 64 * 40 * 2)

__global__ __launch_bounds__(256) void mma_k512(
    const float4* __restrict__ A4, const float4* __restrict__ B4,
    float* __restrict__ out, __half* __restrict__ outh,
    const float* __restrict__ deg, int M)
{
    extern __shared__ float smf[];
    float* As = smf;
    __nv_bfloat16* Bh = (__nv_bfloat16*)(smf + 128 * 36);
    __nv_bfloat16* Bl = Bh + 64 * 40;

    int tid = threadIdx.x, wid = tid >> 5, lane = tid & 31;
    int g = lane >> 2, tg = lane & 3;
    int blk = blockIdx.x;
    int wr = wid * 16;

    float c[8][4];
#pragma unroll
    for (int nt = 0; nt < 8; nt++)
#pragma unroll
        for (int i = 0; i < 4; i++) c[nt][i] = 0.f;

    float4 va[4], vb[2];
#pragma unroll
    for (int it = 0; it < 4; it++) {
        int idx = it * 256 + tid;
        int r = idx >> 3, q = idx & 7;
        int gm = blk * 128 + r;
        va[it] = (gm < M) ? A4[(size_t)gm * 128 + q]
                          : make_float4(0.f, 0.f, 0.f, 0.f);
    }
#pragma unroll
    for (int it = 0; it < 2; it++) {
        int idx = it * 256 + tid;
        int r = idx >> 3, q = idx & 7;
        vb[it] = B4[(size_t)r * 128 + q];
    }

    for (int kc = 0; kc < 16; kc++) {
#pragma unroll
        for (int it = 0; it < 4; it++) {
            int idx = it * 256 + tid;
            int r = idx >> 3, q = idx & 7;
            *(float4*)(As + r * 36 + q * 4) = va[it];
        }
#pragma unroll
        for (int it = 0; it < 2; it++) {
            int idx = it * 256 + tid;
            int r = idx >> 3, q = idx & 7;
            store_b_split(vb[it], Bh, Bl, r * 40 + q * 4);
        }
        __syncthreads();

        if (kc < 15) {
#pragma unroll
            for (int it = 0; it < 4; it++) {
                int idx = it * 256 + tid;
                int r = idx >> 3, q = idx & 7;
                int gm = blk * 128 + r;
                va[it] = (gm < M) ? A4[(size_t)gm * 128 + (kc + 1) * 8 + q]
                                  : make_float4(0.f, 0.f, 0.f, 0.f);
            }
#pragma unroll
            for (int it = 0; it < 2; it++) {
                int idx = it * 256 + tid;
                int r = idx >> 3, q = idx & 7;
                vb[it] = B4[(size_t)r * 128 + (kc + 1) * 8 + q];
            }
        }

#pragma unroll
        for (int s = 0; s < 2; s++)
            mma_step16_m1(As, 36, wr, s * 16, Bh, Bl, 40, s * 16, g, tg, c);
        __syncthreads();
    }

    int r0 = blk * 128 + wr + g;
    int r1 = r0 + 8;
    float d0 = (r0 < M) ? deg[r0] : 1.f;
    float d1 = (r1 < M) ? deg[r1] : 1.f;
    float dv0 = (d0 > 0.f) ? rsqrtf(d0) : 0.f;
    float dv1 = (d1 > 0.f) ? rsqrtf(d1) : 0.f;
#pragma unroll
    for (int nt = 0; nt < 8; nt++) {
        int cb = nt * 8 + 2 * tg;
        if (r0 < M) {
            float v0 = dv0 * c[nt][0], v1 = dv0 * c[nt][1];
            *(float2*)(out + (size_t)r0 * 64 + cb) = make_float2(v0, v1);
            *(__half2*)(outh + (size_t)r0 * 64 + cb) = __floats2half2_rn(v0, v1);
        }
        if (r1 < M) {
            float v2 = dv1 * c[nt][2], v3 = dv1 * c[nt][3];
            *(float2*)(out + (size_t)r1 * 64 + cb) = make_float2(v2, v3);
            *(__half2*)(outh + (size_t)r1 * 64 + cb) = __floats2half2_rn(v2, v3);
        }
    }
}

// ---------------------------------------------------------------------------
// bf16x3 GEMM, K=64, fp16 output. A from fp32 (A4) or fp16 (Ah) source.
// ---------------------------------------------------------------------------
#define K64_SMEM (256 * 68 * 4 + 2 * 64 * 72 * 2)

__global__ __launch_bounds__(256) void mma_k64h(
    const float4* __restrict__ A4, const __half* __restrict__ Ah,
    const float4* __restrict__ B4, __half* __restrict__ outH, int M, int ncols)
{
    extern __shared__ float smf[];
    float* As = smf;
    __nv_bfloat16* Bh = (__nv_bfloat16*)(smf + 256 * 68);
    __nv_bfloat16* Bl = Bh + 64 * 72;

    int tid = threadIdx.x, wid = tid >> 5, lane = tid & 31;
    int g = lane >> 2, tg = lane & 3;
    int blk = blockIdx.x;
    int wr = wid * 32;

#pragma unroll
    for (int it = 0; it < 16; it++) {
        int idx = it * 256 + tid;
        int r = idx >> 4, q = idx & 15;
        int gm = blk * 256 + r;
        float4 v;
        if (gm >= M) {
            v = make_float4(0.f, 0.f, 0.f, 0.f);
        } else if (Ah) {
            uint2 u = *(const uint2*)(Ah + (size_t)gm * 64 + q * 4);
            float2 f0 = __half22float2(*(__half2*)&u.x);
            float2 f1 = __half22float2(*(__half2*)&u.y);
            v = make_float4(f0.x, f0.y, f1.x, f1.y);
        } else {
            v = A4[(size_t)gm * 16 + q];
        }
        *(float4*)(As + r * 68 + q * 4) = v;
    }
    __syncthreads();

    int ntilesc = ncols >> 6;
    for (int ct = 0; ct < ntilesc; ct++) {
#pragma unroll
        for (int it = 0; it < 4; it++) {
            int idx = it * 256 + tid;
            int r = idx >> 4, q = idx & 15;
            float4 v = B4[(size_t)(ct * 64 + r) * 16 + q];
            store_b_split(v, Bh, Bl, r * 72 + q * 4);
        }
        __syncthreads();

        float c[2][8][4];
#pragma unroll
        for (int mt = 0; mt < 2; mt++)
#pragma unroll
            for (int nt = 0; nt < 8; nt++)
#pragma unroll
                for (int i = 0; i < 4; i++) c[mt][nt][i] = 0.f;

#pragma unroll
        for (int s = 0; s < 4; s++)
            mma_step16(As, 68, wr, s * 16, Bh, Bl, 72, s * 16, g, tg, c);

#pragma unroll
        for (int mt = 0; mt < 2; mt++) {
            int r0 = blk * 256 + wr + mt * 16 + g;
            int r1 = r0 + 8;
#pragma unroll
            for (int nt = 0; nt < 8; nt++) {
                int cb = ct * 64 + nt * 8 + 2 * tg;
                if (r0 < M)
                    *(__half2*)(outH + (size_t)r0 * ncols + cb) =
                        __floats2half2_rn(c[mt][nt][0], c[mt][nt][1]);
                if (r1 < M)
                    *(__half2*)(outH + (size_t)r1 * ncols + cb) =
                        __floats2half2_rn(c[mt][nt][2], c[mt][nt][3]);
            }
        }
        __syncthreads();
    }
}

// ---------------------------------------------------------------------------
// CSR gather, fp16 features, 64-wide. 8 lanes/dest, uint4 (16B) loads.
// mode 0: out4 = acc (fp32).  mode 1: xh = relu(dinv*(acc+hs)+b1) (fp16 only).
// ---------------------------------------------------------------------------
__device__ __forceinline__ void h8_acc(uint4 u, float w, float* a) {
    float2 p0 = __half22float2(*(__half2*)&u.x);
    float2 p1 = __half22float2(*(__half2*)&u.y);
    float2 p2 = __half22float2(*(__half2*)&u.z);
    float2 p3 = __half22float2(*(__half2*)&u.w);
    a[0] += w * p0.x; a[1] += w * p0.y;
    a[2] += w * p1.x; a[3] += w * p1.y;
    a[4] += w * p2.x; a[5] += w * p2.y;
    a[6] += w * p3.x; a[7] += w * p3.y;
}

__global__ void gather64h(const int* __restrict__ start, const int* __restrict__ cnt,
                          const float2* __restrict__ sw, const __half* __restrict__ feat,
                          const float4* __restrict__ hs4, const float* __restrict__ dinv,
                          const float* __restrict__ b1, float4* __restrict__ out4,
                          __half* __restrict__ outh, int N, int mode) {
    int gid = blockIdx.x * 256 + threadIdx.x;
    int d = gid >> 3;
    int q = gid & 7;
    if (d >= N) return;

    int j = start[d];
    int end = j + cnt[d];
    float a[8] = {0.f, 0.f, 0.f, 0.f, 0.f, 0.f, 0.f, 0.f};

#pragma unroll 1
    for (; j + 3 < end; j += 4) {
        float2 p0 = __ldg(&sw[j]);
        float2 p1 = __ldg(&sw[j + 1]);
        float2 p2 = __ldg(&sw[j + 2]);
        float2 p3 = __ldg(&sw[j + 3]);
        uint4 u0 = *(const uint4*)(feat + (size_t)__float_as_int(p0.x) * 64 + q * 8);
        uint4 u1 = *(const uint4*)(feat + (size_t)__float_as_int(p1.x) * 64 + q * 8);
        uint4 u2 = *(const uint4*)(feat + (size_t)__float_as_int(p2.x) * 64 + q * 8);
        uint4 u3 = *(const uint4*)(feat + (size_t)__float_as_int(p3.x) * 64 + q * 8);
        h8_acc(u0, p0.y, a);
        h8_acc(u1, p1.y, a);
        h8_acc(u2, p2.y, a);
        h8_acc(u3, p3.y, a);
    }
    for (; j < end; j++) {
        float2 p = __ldg(&sw[j]);
        uint4 u = *(const uint4*)(feat + (size_t)__float_as_int(p.x) * 64 + q * 8);
        h8_acc(u, p.y, a);
    }

    int o = d * 16 + q * 2;
    if (mode == 1) {
        float di = dinv[d];
        float4 h0 = hs4[o];
        float4 h1 = hs4[o + 1];
        float4 bb0 = ((const float4*)b1)[q * 2];
        float4 bb1 = ((const float4*)b1)[q * 2 + 1];
        a[0] = fmaxf(di * (a[0] + h0.x) + bb0.x, 0.f);
        a[1] = fmaxf(di * (a[1] + h0.y) + bb0.y, 0.f);
        a[2] = fmaxf(di * (a[2] + h0.z) + bb0.z, 0.f);
        a[3] = fmaxf(di * (a[3] + h0.w) + bb0.w, 0.f);
        a[4] = fmaxf(di * (a[4] + h1.x) + bb1.x, 0.f);
        a[5] = fmaxf(di * (a[5] + h1.y) + bb1.y, 0.f);
        a[6] = fmaxf(di * (a[6] + h1.z) + bb1.z, 0.f);
        a[7] = fmaxf(di * (a[7] + h1.w) + bb1.w, 0.f);
        __half2 c0 = __floats2half2_rn(a[0], a[1]);
        __half2 c1 = __floats2half2_rn(a[2], a[3]);
        __half2 c2 = __floats2half2_rn(a[4], a[5]);
        __half2 c3 = __floats2half2_rn(a[6], a[7]);
        uint4 uo;
        uo.x = *(uint32_t*)&c0; uo.y = *(uint32_t*)&c1;
        uo.z = *(uint32_t*)&c2; uo.w = *(uint32_t*)&c3;
        *(uint4*)(outh + (size_t)d * 64 + q * 8) = uo;
    } else {
        out4[o]     = make_float4(a[0], a[1], a[2], a[3]);
        out4[o + 1] = make_float4(a[4], a[5], a[6], a[7]);
    }
}

// ---------------------------------------------------------------------------
// GRU elementwise combine (fp16 gates + fp16 state, 2 features/thread)
// ---------------------------------------------------------------------------
__global__ void gru_combine(const __half* __restrict__ gi, const __half* __restrict__ gh,
                            const float* __restrict__ bih, const float* __restrict__ bhh,
                            __half* __restrict__ xh, int n) {
    int i = blockIdx.x * 256 + threadIdx.x;
    if (i >= n * 32) return;
    int nd = i >> 5, f = (i & 31) * 2;
    size_t b = (size_t)nd * 192;

    float2 gir = __half22float2(*(const __half2*)(gi + b + f));
    float2 giz = __half22float2(*(const __half2*)(gi + b + 64 + f));
    float2 gin = __half22float2(*(const __half2*)(gi + b + 128 + f));
    float2 ghr = __half22float2(*(const __half2*)(gh + b + f));
    float2 ghz = __half22float2(*(const __half2*)(gh + b + 64 + f));
    float2 ghn = __half22float2(*(const __half2*)(gh + b + 128 + f));
    float2 bir = *(const float2*)(bih + f);
    float2 biz = *(const float2*)(bih + 64 + f);
    float2 bin = *(const float2*)(bih + 128 + f);
    float2 bhr = *(const float2*)(bhh + f);
    float2 bhz = *(const float2*)(bhh + 64 + f);
    float2 bhn = *(const float2*)(bhh + 128 + f);

    float r0 = 1.f / (1.f + expf(-(gir.x + bir.x + ghr.x + bhr.x)));
    float r1 = 1.f / (1.f + expf(-(gir.y + bir.y + ghr.y + bhr.y)));
    float z0 = 1.f / (1.f + expf(-(giz.x + biz.x + ghz.x + bhz.x)));
    float z1 = 1.f / (1.f + expf(-(giz.y + biz.y + ghz.y + bhz.y)));
    float n0 = tanhf(gin.x + bin.x + r0 * (ghn.x + bhn.x));
    float n1 = tanhf(gin.y + bin.y + r1 * (ghn.y + bhn.y));

    size_t xi = (size_t)nd * 64 + f;
    float2 xv = __half22float2(*(const __half2*)(xh + xi));
    xv.x = (1.f - z0) * n0 + z0 * xv.x;
    xv.y = (1.f - z1) * n1 + z1 * xv.y;
    *(__half2*)(xh + xi) = __floats2half2_rn(xv.x, xv.y);
}

// ---------------------------------------------------------------------------
// GCN2 linear (fp16 state input; writes fp32 + fp16)
// ---------------------------------------------------------------------------
__global__ void gemm_out16(const __half* __restrict__ xh, const float* __restrict__ W2,
                           const float* __restrict__ dinv, float* __restrict__ hs3,
                           __half* __restrict__ hs3h, int nrows) {
    __shared__ float w2s[64 * 16];
    int tid = threadIdx.x;
    for (int i = tid; i < 64 * 16; i += 256) w2s[i] = W2[i];
    __syncthreads();

    int node = blockIdx.x * 16 + (tid >> 4);
    int c = tid & 15;
    if (node >= nrows) return;
    const __half* xr = xh + (size_t)node * 64;
    float s = 0.f;
#pragma unroll
    for (int k = 0; k < 64; k += 2) {
        float2 f = __half22float2(*(const __half2*)(xr + k));
        s += f.x * w2s[k * 16 + c] + f.y * w2s[(k + 1) * 16 + c];
    }
    float v = dinv[node] * s;
    hs3[(size_t)node * 16 + c] = v;
    hs3h[(size_t)node * 16 + c] = __float2half_rn(v);
}

// ---------------------------------------------------------------------------
// Fused GCN2 gather + log_softmax finalize. 4 lanes/dest; shfl reduction.
// ---------------------------------------------------------------------------
__global__ void k_final_gather(const int* __restrict__ start, const int* __restrict__ cnt,
                               const float2* __restrict__ sw,
                               const __half* __restrict__ feat,
                               const float* __restrict__ hs3,
                               const float* __restrict__ dinv,
                               const float* __restrict__ b2,
                               float* __restrict__ out, int N) {
    int gid = blockIdx.x * 256 + threadIdx.x;
    int d = gid >> 2;
    int q = gid & 3;
    if (d >= N) return;

    int j = start[d];
    int end = j + cnt[d];
    float4 acc = make_float4(0.f, 0.f, 0.f, 0.f);

    for (; j + 1 < end; j += 2) {
        float2 p0 = __ldg(&sw[j]);
        float2 p1 = __ldg(&sw[j + 1]);
        uint2 u0 = *(const uint2*)(feat + (size_t)__float_as_int(p0.x) * 16 + q * 4);
        uint2 u1 = *(const uint2*)(feat + (size_t)__float_as_int(p1.x) * 16 + q * 4);
        float2 a0 = __half22float2(*(__half2*)&u0.x), b0 = __half22float2(*(__half2*)&u0.y);
        float2 a1 = __half22float2(*(__half2*)&u1.x), b1v = __half22float2(*(__half2*)&u1.y);
        acc.x += p0.y * a0.x; acc.y += p0.y * a0.y; acc.z += p0.y * b0.x; acc.w += p0.y * b0.y;
        acc.x += p1.y * a1.x; acc.y += p1.y * a1.y; acc.z += p1.y * b1v.x; acc.w += p1.y * b1v.y;
    }
    if (j < end) {
        float2 p = __ldg(&sw[j]);
        uint2 u = *(const uint2*)(feat + (size_t)__float_as_int(p.x) * 16 + q * 4);
        float2 a = __half22float2(*(__half2*)&u.x), b = __half22float2(*(__half2*)&u.y);
        acc.x += p.y * a.x; acc.y += p.y * a.y;
        acc.z += p.y * b.x; acc.w += p.y * b.y;
    }

    float di = dinv[d];
    float4 h = *(const float4*)(hs3 + (size_t)d * 16 + q * 4);
    float4 bb = ((const float4*)b2)[q];
    float v0 = di * (acc.x + h.x) + bb.x;
    float v1 = di * (acc.y + h.y) + bb.y;
    float v2 = di * (acc.z + h.z) + bb.z;
    float v3 = di * (acc.w + h.w) + bb.w;

    float mx = fmaxf(fmaxf(v0, v1), fmaxf(v2, v3));
    mx = fmaxf(mx, __shfl_xor_sync(0xFFFFFFFFu, mx, 1));
    mx = fmaxf(mx, __shfl_xor_sync(0xFFFFFFFFu, mx, 2));
    float sum = expf(v0 - mx) + expf(v1 - mx) + expf(v2 - mx) + expf(v3 - mx);
    sum += __shfl_xor_sync(0xFFFFFFFFu, sum, 1);
    sum += __shfl_xor_sync(0xFFFFFFFFu, sum, 2);
    float l = mx + logf(sum);

    *(float4*)(out + (size_t)d * 16 + q * 4) =
        make_float4(v0 - l, v1 - l, v2 - l, v3 - l);
}

// ---------------------------------------------------------------------------
// Launch sequence with dual-stream overlap (capture-safe fork/join).
// ---------------------------------------------------------------------------
extern "C" void kernel_launch(void* const* d_in, const int* in_sizes, int n_in,
                              void* d_out, int out_size) {
    const float* x   = (const float*)d_in[0];
    const int*   ei  = (const int*)d_in[1];
    const float* ew  = (const float*)d_in[2];
    const float* W1  = (const float*)d_in[3];
    const float* b1  = (const float*)d_in[4];
    const float* Wg  = (const float*)d_in[5];
    const float* Wih = (const float*)d_in[6];
    const float* Whh = (const float*)d_in[7];
    const float* bih = (const float*)d_in[8];
    const float* bhh = (const float*)d_in[9];
    const float* W2  = (const float*)d_in[10];
    const float* b2  = (const float*)d_in[11];
    float* out = (float*)d_out;

    const int N = in_sizes[0] / 512;
    const int E = in_sizes[2];
    const int* row = ei;
    const int* col = ei + E;

    float *p_deg, *p_dinv, *p_hs, *p_acc, *p_hs3, *p_W1T, *p_Wf;
    __half *p_hsh, *p_xh, *p_hs3h, *p_gi, *p_gh;
    int *p_cnt, *p_start, *p_cursor, *p_csum;
    float2* p_sw;
    cudaGetSymbolAddress((void**)&p_deg,    g_deg);
    cudaGetSymbolAddress((void**)&p_dinv,   g_dinv);
    cudaGetSymbolAddress((void**)&p_hs,     g_hs);
    cudaGetSymbolAddress((void**)&p_hsh,    g_hsh);
    cudaGetSymbolAddress((void**)&p_xh,     g_xh);
    cudaGetSymbolAddress((void**)&p_acc,    g_acc);
    cudaGetSymbolAddress((void**)&p_hs3,    g_hs3);
    cudaGetSymbolAddress((void**)&p_hs3h,   g_hs3h);
    cudaGetSymbolAddress((void**)&p_gi,     g_gi);
    cudaGetSymbolAddress((void**)&p_gh,     g_gh);
    cudaGetSymbolAddress((void**)&p_W1T,    g_W1T);
    cudaGetSymbolAddress((void**)&p_Wf,     g_Wf);
    cudaGetSymbolAddress((void**)&p_cnt,    g_cnt);
    cudaGetSymbolAddress((void**)&p_start,  g_start);
    cudaGetSymbolAddress((void**)&p_cursor, g_cursor);
    cudaGetSymbolAddress((void**)&p_csum,   g_csum);
    cudaGetSymbolAddress((void**)&p_sw,     g_sw);

    cudaFuncSetAttribute(mma_k512, cudaFuncAttributeMaxDynamicSharedMemorySize, K512_SMEM);
    cudaFuncSetAttribute(mma_k64h, cudaFuncAttributeMaxDynamicSharedMemorySize, K64_SMEM);

    static cudaStream_t s2 = 0;
    static cudaEvent_t evf[3], evj[3];
    if (s2 == 0) {
        cudaStreamCreateWithFlags(&s2, cudaStreamNonBlocking);
        for (int i = 0; i < 3; i++) {
            cudaEventCreateWithFlags(&evf[i], cudaEventDisableTiming);
            cudaEventCreateWithFlags(&evj[i], cudaEventDisableTiming);
        }
    }

    const int nblkN    = (N + 255) / 256;
    const int nblkE    = (E + 255) / 256;
    const int nblkM128 = (N + 127) / 128;
    const int nblkM256 = (N + 255) / 256;
    const int nblk16   = (N + 15) / 16;
    const int nchunks  = (N + CHUNK - 1) / CHUNK;
    const int nblkG64  = (N * 8 + 255) / 256;
    const int nblkG4   = (N * 4 + 255) / 256;
    const int nblkC    = (N * 32 + 255) / 256;

    // --- main stream: prerequisites for the big GEMM ---
    k_T512<<<(512 * 64 + 255) / 256, 256>>>(W1, p_W1T);
    k_init<<<nblkN, 256>>>(p_deg, p_cnt, N);
    k_deg_hist<<<nblkE, 256>>>(col, ew, p_deg, p_cnt, E);

    // fork: CSR build + weight prep on s2, concurrent with mma_k512
    cudaEventRecord(evf[0], 0);
    cudaStreamWaitEvent(s2, evf[0], 0);

    mma_k512<<<nblkM128, 256, K512_SMEM>>>((const float4*)x, (const float4*)p_W1T,
                                           p_hs, p_hsh, p_deg, N);

    k_dinv<<<nblkN, 256, 0, s2>>>(p_deg, p_dinv, N);
    k_fuseW<<<(2 * 192 * 64 + 255) / 256, 256, 0, s2>>>(Wg, Wih, p_Wf);
    k_scan_chunk<<<nchunks, CHUNK, 0, s2>>>(p_cnt, p_start, p_csum, N);
    k_scan_sums<<<1, 128, 0, s2>>>(p_csum, nchunks);
    k_scan_add<<<nblkN, 256, 0, s2>>>(p_start, p_cursor, p_csum, N);
    k_reorder<<<nblkE, 256, 0, s2>>>(row, col, ew, p_cursor, p_sw, E);
    cudaEventRecord(evj[0], s2);
    cudaStreamWaitEvent(0, evj[0], 0);

    // GCN1 gather: xh = relu(...) (fp16 state only)
    gather64h<<<nblkG64, 256>>>(p_start, p_cnt, p_sw, p_hsh,
                                (const float4*)p_hs, p_dinv, b1,
                                (float4*)0, p_xh, N, 1);

    // GatedGraphConv: 2 layers; gh-GEMM overlapped on s2
    for (int l = 0; l < 2; l++) {
        cudaEventRecord(evf[1 + l], 0);
        cudaStreamWaitEvent(s2, evf[1 + l], 0);
        // s2: gh = x @ Whh^T (fp16 A, fp16 out, 192 cols)
        mma_k64h<<<nblkM256, 256, K64_SMEM, s2>>>((const float4*)0, p_xh,
                                                  (const float4*)Whh, p_gh, N, 192);
        // main: xagg = gather(xh); gi = xagg @ Wf_l (fp32 A, fp16 out)
        gather64h<<<nblkG64, 256>>>(p_start, p_cnt, p_sw, p_xh,
                                    (const float4*)0, (const float*)0, (const float*)0,
                                    (float4*)p_acc, (__half*)0, N, 0);
        mma_k64h<<<nblkM256, 256, K64_SMEM>>>((const float4*)p_acc, (const __half*)0,
                                              (const float4*)(p_Wf + (size_t)l * 192 * 64),
                                              p_gi, N, 192);
        cudaEventRecord(evj[1 + l], s2);
        cudaStreamWaitEvent(0, evj[1 + l], 0);
        gru_combine<<<nblkC, 256>>>(p_gi, p_gh, bih, bhh, p_xh, N);
    }

    // GCN layer 2 + fused gather/log_softmax
    gemm_out16<<<nblk16, 256>>>(p_xh, W2, p_dinv, p_hs3, p_hs3h, N);
    k_final_gather<<<nblkG4, 256>>>(p_start, p_cnt, p_sw, p_hs3h, p_hs3,
                                    p_dinv, b2, out, N);
}